// round 6
// baseline (speedup 1.0000x reference)
#include <cuda_runtime.h>
#include <cuda_fp16.h>
#include <cstdint>
#include <cstddef>

// ---------------- problem constants ----------------
static constexpr int Bb = 64, Tt = 2048, Jj = 128, Dd = 256;
static constexpr int TILE_M = 128;

// ---------------- smem layout (bytes) ----------------
// B (U) tile: 128 rows x 256 halves = 512B/row, XOR-swizzled, no pad.
// A (H) chunk: 128 rows x 64 halves = 128B/row, XOR-swizzled, double buffered.
static constexpr int SM_W  = 0;                    // 768 f32 (w1|w2|w3)
static constexpr int SM_SH = 3072;                 // 128 f32
static constexpr int SM_SU = 3584;                 // 128 f32
static constexpr int SM_B  = 4096;                 // 65536 B
static constexpr int SM_A0 = SM_B + 128 * 512;     // 69632
static constexpr int SM_A1 = SM_A0 + 128 * 128;    // 86016
static constexpr int SMEM_BYTES = SM_A1 + 128 * 128; // 102400

// ---------------- helpers ----------------
__device__ __forceinline__ uint32_t smem_u32(const void* p) {
    uint32_t a;
    asm("{ .reg .u64 t; cvta.to.shared.u64 t, %1; cvt.u32.u64 %0, t; }"
        : "=r"(a) : "l"(p));
    return a;
}

__device__ __forceinline__ uint32_t pk(float a, float b) {
    __half2 h = __floats2half2_rn(a, b);
    return *reinterpret_cast<uint32_t*>(&h);
}

__device__ __forceinline__ void ldm_x4(uint32_t* r, uint32_t addr) {
    asm volatile("ldmatrix.sync.aligned.m8n8.x4.shared.b16 {%0,%1,%2,%3}, [%4];"
                 : "=r"(r[0]), "=r"(r[1]), "=r"(r[2]), "=r"(r[3])
                 : "r"(addr));
}

__device__ __forceinline__ void mma16816(float* c, const uint32_t* a,
                                         const uint32_t* b) {
    asm volatile(
        "mma.sync.aligned.m16n8k16.row.col.f32.f16.f16.f32 "
        "{%0,%1,%2,%3}, {%4,%5,%6,%7}, {%8,%9}, {%0,%1,%2,%3};"
        : "+f"(c[0]), "+f"(c[1]), "+f"(c[2]), "+f"(c[3])
        : "r"(a[0]), "r"(a[1]), "r"(a[2]), "r"(a[3]), "r"(b[0]), "r"(b[1]));
}

// Load one K=64 H chunk into registers (issued early; latency hides under MMA).
__device__ __forceinline__ void ldg_chunk(const float* __restrict__ Hb, int c,
                                          int wid, int sub, int aa, float4* pre) {
#pragma unroll
    for (int rb = 0; rb < 4; rb++) {
        const int row = wid * 16 + rb * 4 + sub;
        const float* p = Hb + (size_t)row * Dd + c * 64 + aa * 8;
        pre[rb * 2]     = *(const float4*)(p);
        pre[rb * 2 + 1] = *(const float4*)(p + 4);
    }
}

// Scale by w3, convert fp16, STS.128 swizzled; fuse s_h partial dot (raw H . w1).
__device__ __forceinline__ void sts_chunk(char* smem, int base, int c, int wid,
                                          int sub, int aa,
                                          const float* __restrict__ w1s,
                                          const float* __restrict__ w3s,
                                          const float4* pre, float* acch) {
    const int k = c * 64 + aa * 8;
    const float4 q0 = *(const float4*)(w1s + k);
    const float4 q1 = *(const float4*)(w1s + k + 4);
    const float4 r0 = *(const float4*)(w3s + k);
    const float4 r1 = *(const float4*)(w3s + k + 4);
#pragma unroll
    for (int rb = 0; rb < 4; rb++) {
        const int row = wid * 16 + rb * 4 + sub;
        const float4 v0 = pre[rb * 2];
        const float4 v1 = pre[rb * 2 + 1];
        acch[rb] += v0.x * q0.x + v0.y * q0.y + v0.z * q0.z + v0.w * q0.w +
                    v1.x * q1.x + v1.y * q1.y + v1.z * q1.z + v1.w * q1.w;
        uint4 hv;
        hv.x = pk(v0.x * r0.x, v0.y * r0.y);
        hv.y = pk(v0.z * r0.z, v0.w * r0.w);
        hv.z = pk(v1.x * r1.x, v1.y * r1.y);
        hv.w = pk(v1.z * r1.z, v1.w * r1.w);
        const int byte = base + row * 128 + ((aa ^ (row & 7)) << 4);
        *(uint4*)(smem + byte) = hv;
    }
}

// ---------------- kernel ----------------
__global__ void __launch_bounds__(256, 1)
sim_kernel(const float* __restrict__ H, const float* __restrict__ U,
           const float* __restrict__ w, float* __restrict__ out) {
    extern __shared__ char smem[];
    const uint32_t sb = smem_u32(smem);
    float* ws  = (float*)(smem + SM_W);
    float* shs = (float*)(smem + SM_SH);
    float* sus = (float*)(smem + SM_SU);

    const int tid = threadIdx.x;
    const int wid = tid >> 5, lid = tid & 31;
    const int sub = lid >> 3, aa = lid & 7;   // 4 rows x 8 16B-atoms per warp-iter
    const int b   = blockIdx.x >> 4;
    const int t0  = (blockIdx.x & 15) * TILE_M;
    const float* Ub = U + (size_t)b * Jj * Dd;
    const float* Hb = H + ((size_t)b * Tt + t0) * Dd;

    for (int i = tid; i < 3 * Dd; i += 256) ws[i] = w[i];
    __syncthreads();
    const float* w1s = ws;
    const float* w2s = ws + Dd;
    const float* w3s = ws + 2 * Dd;

    // ===== U tile: load fp32 -> fp16 swizzled smem, fused s_u dot =====
    {
        float accu[4] = {0.f, 0.f, 0.f, 0.f};
#pragma unroll
        for (int rb = 0; rb < 4; rb++) {
            const int row = wid * 16 + rb * 4 + sub;   // j index
#pragma unroll
            for (int ia = 0; ia < 4; ia++) {
                const int a = ia * 8 + aa;             // 16B-atom index (k = a*8)
                const float* p = Ub + (size_t)row * Dd + a * 8;
                const float4 v0 = *(const float4*)(p);
                const float4 v1 = *(const float4*)(p + 4);
                const float4 q0 = *(const float4*)(w2s + a * 8);
                const float4 q1 = *(const float4*)(w2s + a * 8 + 4);
                accu[rb] += v0.x * q0.x + v0.y * q0.y + v0.z * q0.z + v0.w * q0.w +
                            v1.x * q1.x + v1.y * q1.y + v1.z * q1.z + v1.w * q1.w;
                uint4 hv;
                hv.x = pk(v0.x, v0.y); hv.y = pk(v0.z, v0.w);
                hv.z = pk(v1.x, v1.y); hv.w = pk(v1.z, v1.w);
                const int byte = SM_B + row * 512 +
                                 (((a & 24) | ((a & 7) ^ (row & 7))) << 4);
                *(uint4*)(smem + byte) = hv;
            }
        }
#pragma unroll
        for (int rb = 0; rb < 4; rb++) {
            float r = accu[rb];
            r += __shfl_xor_sync(0xffffffffu, r, 1);
            r += __shfl_xor_sync(0xffffffffu, r, 2);
            r += __shfl_xor_sync(0xffffffffu, r, 4);
            if (aa == 0) sus[wid * 16 + rb * 4 + sub] = r;
        }
    }

    // ===== H chunk 0 =====
    float acch[4] = {0.f, 0.f, 0.f, 0.f};
    float4 pre[8];
    ldg_chunk(Hb, 0, wid, sub, aa, pre);
    sts_chunk(smem, SM_A0, 0, wid, sub, aa, w1s, w3s, pre, acch);
    __syncthreads();

    // ===== mainloop: MMA over K chunks, prefetch next chunk under MMA =====
    const int wm = (wid & 3) * 32;
    const int wn = (wid >> 2) * 64;
    float acc[2][8][4];
#pragma unroll
    for (int mt = 0; mt < 2; mt++)
#pragma unroll
        for (int nt = 0; nt < 8; nt++)
#pragma unroll
            for (int r = 0; r < 4; r++) acc[mt][nt][r] = 0.f;

    for (int c = 0; c < 4; c++) {
        if (c < 3) ldg_chunk(Hb, c + 1, wid, sub, aa, pre);  // LDGs in flight
        const int abase = (c & 1) ? SM_A1 : SM_A0;
#pragma unroll
        for (int k16 = 0; k16 < 4; k16++) {
            uint32_t af[2][4];
#pragma unroll
            for (int mt = 0; mt < 2; mt++) {
                const int row  = wm + mt * 16 + (lid & 15);
                const int atom = k16 * 2 + (lid >> 4);
                ldm_x4(af[mt],
                       sb + abase + row * 128 + ((atom ^ (row & 7)) << 4));
            }
            uint32_t bf[8][2];
#pragma unroll
            for (int nt2 = 0; nt2 < 4; nt2++) {
                const int n = wn + nt2 * 16 + ((lid >> 4) << 3) + (lid & 7);
                const int a = c * 8 + k16 * 2 + ((lid >> 3) & 1);
                uint32_t r[4];
                ldm_x4(r, sb + SM_B + n * 512 +
                              (((a & 24) | ((a & 7) ^ (n & 7))) << 4));
                bf[nt2 * 2][0] = r[0]; bf[nt2 * 2][1] = r[1];
                bf[nt2 * 2 + 1][0] = r[2]; bf[nt2 * 2 + 1][1] = r[3];
            }
#pragma unroll
            for (int mt = 0; mt < 2; mt++)
#pragma unroll
                for (int nt = 0; nt < 8; nt++)
                    mma16816(acc[mt][nt], af[mt], bf[nt]);
        }
        if (c < 3) {
            sts_chunk(smem, ((c + 1) & 1) ? SM_A1 : SM_A0, c + 1, wid, sub, aa,
                      w1s, w3s, pre, acch);
            __syncthreads();
        }
    }

    // ===== s_h reduce + publish =====
#pragma unroll
    for (int rb = 0; rb < 4; rb++) {
        float r = acch[rb];
        r += __shfl_xor_sync(0xffffffffu, r, 1);
        r += __shfl_xor_sync(0xffffffffu, r, 2);
        r += __shfl_xor_sync(0xffffffffu, r, 4);
        if (aa == 0) shs[wid * 16 + rb * 4 + sub] = r;
    }
    __syncthreads();

    // ===== epilogue: acc + s_h[m] + s_u[n] -> out =====
    float* outp = out + ((size_t)b * Tt + t0) * Jj;
#pragma unroll
    for (int mt = 0; mt < 2; mt++) {
        const int m0 = wm + mt * 16 + (lid >> 2);
        const float sh0 = shs[m0];
        const float sh1 = shs[m0 + 8];
#pragma unroll
        for (int nt = 0; nt < 8; nt++) {
            const int n = wn + nt * 8 + (lid & 3) * 2;
            const float2 su = *(const float2*)(sus + n);
            float2 o0, o1;
            o0.x = acc[mt][nt][0] + sh0 + su.x;
            o0.y = acc[mt][nt][1] + sh0 + su.y;
            o1.x = acc[mt][nt][2] + sh1 + su.x;
            o1.y = acc[mt][nt][3] + sh1 + su.y;
            *(float2*)(outp + (size_t)m0 * Jj + n) = o0;
            *(float2*)(outp + (size_t)(m0 + 8) * Jj + n) = o1;
        }
    }
}

// ---------------- launch ----------------
extern "C" void kernel_launch(void* const* d_in, const int* in_sizes, int n_in,
                              void* d_out, int out_size) {
    const float* H = (const float*)d_in[0];
    const float* U = (const float*)d_in[1];
    const float* w = (const float*)d_in[2];
    float* out = (float*)d_out;

    cudaFuncSetAttribute(sim_kernel, cudaFuncAttributeMaxDynamicSharedMemorySize,
                         SMEM_BYTES);
    sim_kernel<<<Bb * (Tt / TILE_M), 256, SMEM_BYTES>>>(H, U, w, out);
}